// round 13
// baseline (speedup 1.0000x reference)
#include <cuda_runtime.h>
#include <cuda_fp16.h>

#define NN 50000
#define EE 1600000
#define KHOPS 16
#define NBLK ((NN + 1023) / 1024)
#define PADCAP (EE + 8 * NN + 16)
#define HOPBLOCKS 592                 // 148 SMs * 4 resident blocks
#define NWARPS (HOPBLOCKS * 8)

// ---- device scratch (no allocations allowed) ----
__device__ int      g_deg[NN];
__device__ int      g_rowptr[NN + 1];
__device__ int      g_cursor[NN];
__device__ unsigned short g_col16[PADCAP];
__device__ float    g_dinv2[NN];    // (deg+1)^-1
__device__ float    g_rdinv[NN];    // (deg+1)^+1/2
__device__ float    g_dinv[NN];     // (deg+1)^-1/2
__device__ int      g_bsum[NBLK];
__device__ __half   g_x[KHOPS + 1][(NN + 1) * 128];  // y-states, fp16

__global__ void k_zero_deg() {
    int i = blockIdx.x * blockDim.x + threadIdx.x;
    if (i < NN) g_deg[i] = 0;
}

__global__ void k_degree(const int* __restrict__ dst) {
    int e = blockIdx.x * blockDim.x + threadIdx.x;
    if (e < EE) atomicAdd(&g_deg[dst[e]], 1);
}

// ---- scan phase 1 (+ fused dinv). Row length = deg+1 (self), padded to 8. ----
__global__ void k_scan1() {
    __shared__ int tmp[1024];
    int t = threadIdx.x;
    int i = blockIdx.x * 1024 + t;
    int dg = (i < NN) ? g_deg[i] : 0;
    if (i < NN) {
        float d = (float)(dg + 1);
        float r = rsqrtf(d);
        g_dinv[i]  = r;
        g_dinv2[i] = r * r;
        g_rdinv[i] = sqrtf(d);
    }
    int v = (i < NN) ? ((dg + 1 + 7) & ~7) : 0;
    tmp[t] = v;
    __syncthreads();
#pragma unroll
    for (int off = 1; off < 1024; off <<= 1) {
        int add = (t >= off) ? tmp[t - off] : 0;
        __syncthreads();
        tmp[t] += add;
        __syncthreads();
    }
    if (i < NN) g_rowptr[i] = tmp[t] - v;
    if (t == 1023) g_bsum[blockIdx.x] = tmp[t];
}

__global__ void k_scan2() {          // 64-thread parallel scan over NBLK block sums
    __shared__ int tmp[64];
    int t = threadIdx.x;
    int v = (t < NBLK) ? g_bsum[t] : 0;
    tmp[t] = v;
    __syncthreads();
#pragma unroll
    for (int off = 1; off < 64; off <<= 1) {
        int add = (t >= off) ? tmp[t - off] : 0;
        __syncthreads();
        tmp[t] += add;
        __syncthreads();
    }
    if (t < NBLK) g_bsum[t] = tmp[t] - v;
    if (t == 63) g_rowptr[NN] = tmp[t];
}

__global__ void k_scan3() {
    int i = blockIdx.x * 1024 + threadIdx.x;
    if (i < NN) {
        int r = g_rowptr[i] + g_bsum[blockIdx.x];
        g_rowptr[i] = r;
        g_cursor[i] = r;
    }
}

__global__ void k_fill(const int* __restrict__ src, const int* __restrict__ dst) {
    int e = blockIdx.x * blockDim.x + threadIdx.x;
    if (e < EE) {
        int d = dst[e];
        int p = atomicAdd(&g_cursor[d], 1);
        g_col16[p] = (unsigned short)src[e];
    }
}

// deterministic: warp-per-row SMEM rank sort; append self id; pad with 0xFFFF sentinel
__global__ void __launch_bounds__(256) k_sort() {
    __shared__ unsigned short buf[8][160];
    int warp = threadIdx.x >> 5, lane = threadIdx.x & 31;
    int r = blockIdx.x * 8 + warp;
    if (r >= NN) return;
    int beg  = g_rowptr[r];
    int deg  = g_deg[r];
    int plen = g_rowptr[r + 1] - beg;
    if (deg <= 160) {
        for (int i = lane; i < deg; i += 32) buf[warp][i] = g_col16[beg + i];
        __syncwarp();
        for (int i = lane; i < deg; i += 32) {
            int v = buf[warp][i];
            int rank = 0;
            for (int j = 0; j < deg; j++) {
                int u = buf[warp][j];
                rank += (u < v) || (u == v && j < i);
            }
            g_col16[beg + rank] = (unsigned short)v;
        }
    } else if (lane == 0) {          // practically unreachable fallback
        for (int i = beg + 1; i < beg + deg; i++) {
            unsigned short key = g_col16[i];
            int j = i - 1;
            while (j >= beg && g_col16[j] > key) { g_col16[j + 1] = g_col16[j]; j--; }
            g_col16[j + 1] = key;
        }
    }
    if (lane == 0) g_col16[beg + deg] = (unsigned short)r;       // self loop
    for (int i = deg + 1 + lane; i < plen; i += 32)
        g_col16[beg + i] = (unsigned short)0xFFFF;               // sentinel: no load
}

// y0 = dinv * x0 -> fp16
__global__ void k_init(const float4* __restrict__ x0) {
    int i = blockIdx.x * blockDim.x + threadIdx.x;
    if (i < NN * 32) {
        int row = i >> 5;
        float d = g_dinv[row];
        float4 v = x0[i];
        uint2 u;
        __half2 lo = __floats2half2_rn(d * v.x, d * v.y);
        __half2 hi = __floats2half2_rn(d * v.z, d * v.w);
        u.x = *reinterpret_cast<unsigned*>(&lo);
        u.y = *reinterpret_cast<unsigned*>(&hi);
        ((uint2*)g_x[0])[i] = u;
    }
}

__device__ __forceinline__ void acc2(float& ax, float& ay, float& az, float& aw, uint2 u) {
    __half2 h0 = *reinterpret_cast<__half2*>(&u.x);
    __half2 h1 = *reinterpret_cast<__half2*>(&u.y);
    float2 f0 = __half22float2(h0);
    float2 f1 = __half22float2(h1);
    ax += f0.x; ay += f0.y; az += f1.x; aw += f1.y;
}

__device__ __forceinline__ void acc8(float* a, uint4 u) {
    acc2(a[0], a[1], a[2], a[3], make_uint2(u.x, u.y));
    acc2(a[4], a[5], a[6], a[7], make_uint2(u.z, u.w));
}

// hop: static strided node assignment (deterministic, no atomics).
// Warp per node; lanes 0-15 handle EVEN list slots, 16-31 ODD slots.
// Per iter: one uint4 id-load (8 ids) -> 4 predicated LDG.128 per lane.
// Sentinel ids (>=NN) are predicated off: zero traffic for padding.
__global__ void __launch_bounds__(256, 4) k_hop(int k) {
    const __half* __restrict__ xin = g_x[k - 1];
    __half* __restrict__ xout = g_x[k];
    int gwarp = (blockIdx.x * blockDim.x + threadIdx.x) >> 5;
    int lane = threadIdx.x & 31;
    int hi   = lane >> 4;        // even/odd slot class
    int c16  = lane & 15;        // 16-byte chunk of the 256B row

    for (int n = gwarp; n < NN; n += NWARPS) {
        float a[8];
#pragma unroll
        for (int q = 0; q < 8; q++) a[q] = 0.f;
        int j   = g_rowptr[n];
        int end = g_rowptr[n + 1];
        for (; j < end; j += 8) {               // 8 list slots per iter
            uint4 cc = *(const uint4*)(g_col16 + j);
            int c0 = hi ? (int)(cc.x >> 16) : (int)(cc.x & 0xFFFF);
            int c1 = hi ? (int)(cc.y >> 16) : (int)(cc.y & 0xFFFF);
            int c2 = hi ? (int)(cc.z >> 16) : (int)(cc.z & 0xFFFF);
            int c3 = hi ? (int)(cc.w >> 16) : (int)(cc.w & 0xFFFF);
            uint4 v0 = make_uint4(0u, 0u, 0u, 0u);
            uint4 v1 = make_uint4(0u, 0u, 0u, 0u);
            uint4 v2 = make_uint4(0u, 0u, 0u, 0u);
            uint4 v3 = make_uint4(0u, 0u, 0u, 0u);
            if (c0 < NN) v0 = ((const uint4*)(xin + (size_t)c0 * 128))[c16];
            if (c1 < NN) v1 = ((const uint4*)(xin + (size_t)c1 * 128))[c16];
            if (c2 < NN) v2 = ((const uint4*)(xin + (size_t)c2 * 128))[c16];
            if (c3 < NN) v3 = ((const uint4*)(xin + (size_t)c3 * 128))[c16];
            acc8(a, v0);
            acc8(a, v1);
            acc8(a, v2);
            acc8(a, v3);
        }
        // combine even/odd halves (fixed order -> deterministic)
#pragma unroll
        for (int q = 0; q < 8; q++)
            a[q] += __shfl_xor_sync(0xffffffffu, a[q], 16);
        if (hi == 0) {
            float s2 = g_dinv2[n];
            uint4 o;
            __half2 p0 = __floats2half2_rn(s2 * a[0], s2 * a[1]);
            __half2 p1 = __floats2half2_rn(s2 * a[2], s2 * a[3]);
            __half2 p2 = __floats2half2_rn(s2 * a[4], s2 * a[5]);
            __half2 p3 = __floats2half2_rn(s2 * a[6], s2 * a[7]);
            o.x = *reinterpret_cast<unsigned*>(&p0);
            o.y = *reinterpret_cast<unsigned*>(&p1);
            o.z = *reinterpret_cast<unsigned*>(&p2);
            o.w = *reinterpret_cast<unsigned*>(&p3);
            ((uint4*)(xout + (size_t)n * 128))[c16] = o;
        }
    }
}

// Fused finalize + GEMM. h[m,:] = 0.05*x0 + (0.95/16)*rdinv*sum_k y_k, built in SMEM,
// then C[m,o] = sum_d h[m,d]*W[o,d] + bias[o]. 64-row tile.
__global__ void __launch_bounds__(256) k_gemm(const float4* __restrict__ x0,
                                              const float* __restrict__ Wt,
                                              const float* __restrict__ bias,
                                              float* __restrict__ out) {
    __shared__ float Hs[64][129];
    __shared__ float Ws[128][34];
    int tid = threadIdx.x;
    int row0 = blockIdx.x * 64;
    const float cf = 0.95f / 16.0f;

#pragma unroll
    for (int q = 0; q < 8; q++) {
        int p = tid + 256 * q;          // 0..2047
        int r = p >> 5, c4 = p & 31;
        int gr = row0 + r;
        float hx = 0.f, hy = 0.f, hz = 0.f, hw = 0.f;
        if (gr < NN) {
            float sx = 0.f, sy = 0.f, sz = 0.f, sw = 0.f;
#pragma unroll
            for (int k = 1; k <= KHOPS; k++) {
                uint2 u = ((const uint2*)(g_x[k] + (size_t)gr * 128))[c4];
                acc2(sx, sy, sz, sw, u);
            }
            float rd = g_rdinv[gr];
            float4 v = x0[gr * 32 + c4];
            hx = fmaf(cf * rd, sx, 0.05f * v.x);
            hy = fmaf(cf * rd, sy, 0.05f * v.y);
            hz = fmaf(cf * rd, sz, 0.05f * v.z);
            hw = fmaf(cf * rd, sw, 0.05f * v.w);
        }
        Hs[r][c4 * 4 + 0] = hx; Hs[r][c4 * 4 + 1] = hy;
        Hs[r][c4 * 4 + 2] = hz; Hs[r][c4 * 4 + 3] = hw;
    }

    int tx = tid & 15;    // out cols tx*8..+7
    int ty = tid >> 4;    // rows ty*4..+3
    float acc[4][8];
#pragma unroll
    for (int r = 0; r < 4; r++)
#pragma unroll
        for (int o = 0; o < 8; o++) acc[r][o] = 0.f;

    const float4* w4 = (const float4*)Wt;
    __syncthreads();
    for (int kc = 0; kc < 4; kc++) {
#pragma unroll
        for (int q = 0; q < 4; q++) {
            int idx = tid * 4 + q;       // 0..1023
            int o = idx >> 3, c4 = idx & 7;
            float4 v = w4[o * 32 + kc * 8 + c4];
            Ws[o][c4 * 4 + 0] = v.x; Ws[o][c4 * 4 + 1] = v.y;
            Ws[o][c4 * 4 + 2] = v.z; Ws[o][c4 * 4 + 3] = v.w;
        }
        __syncthreads();
#pragma unroll
        for (int kk = 0; kk < 32; kk++) {
            int kg = kc * 32 + kk;
            float hreg[4], wreg[8];
#pragma unroll
            for (int r = 0; r < 4; r++) hreg[r] = Hs[ty * 4 + r][kg];
#pragma unroll
            for (int o = 0; o < 8; o++) wreg[o] = Ws[tx * 8 + o][kk];
#pragma unroll
            for (int r = 0; r < 4; r++)
#pragma unroll
                for (int o = 0; o < 8; o++)
                    acc[r][o] = fmaf(hreg[r], wreg[o], acc[r][o]);
        }
        __syncthreads();
    }

    float b[8];
#pragma unroll
    for (int o = 0; o < 8; o++) b[o] = bias[tx * 8 + o];
    float4* out4 = (float4*)out;
#pragma unroll
    for (int r = 0; r < 4; r++) {
        int gr = row0 + ty * 4 + r;
        if (gr < NN) {
            float4 lo = make_float4(acc[r][0] + b[0], acc[r][1] + b[1],
                                    acc[r][2] + b[2], acc[r][3] + b[3]);
            float4 hi4 = make_float4(acc[r][4] + b[4], acc[r][5] + b[5],
                                     acc[r][6] + b[6], acc[r][7] + b[7]);
            out4[gr * 32 + tx * 2 + 0] = lo;
            out4[gr * 32 + tx * 2 + 1] = hi4;
        }
    }
}

extern "C" void kernel_launch(void* const* d_in, const int* in_sizes, int n_in,
                              void* d_out, int out_size) {
    const float* x0   = (const float*)d_in[0];
    const int*   ei   = (const int*)d_in[1];
    const float* Wt   = (const float*)d_in[2];
    const float* bias = (const float*)d_in[3];
    float*       out  = (float*)d_out;
    const int* src = ei;
    const int* dst = ei + EE;

    k_zero_deg<<<(NN + 255) / 256, 256>>>();
    k_degree<<<(EE + 255) / 256, 256>>>(dst);
    k_scan1<<<NBLK, 1024>>>();
    k_scan2<<<1, 64>>>();
    k_scan3<<<NBLK, 1024>>>();
    k_fill<<<(EE + 255) / 256, 256>>>(src, dst);
    k_sort<<<(NN + 7) / 8, 256>>>();
    k_init<<<(NN * 32 + 255) / 256, 256>>>((const float4*)x0);

    for (int k = 1; k <= KHOPS; k++)
        k_hop<<<HOPBLOCKS, 256>>>(k);

    k_gemm<<<(NN + 63) / 64, 256>>>((const float4*)x0, Wt, bias, out);
}

// round 14
// speedup vs baseline: 1.0025x; 1.0025x over previous
#include <cuda_runtime.h>
#include <cuda_fp16.h>

#define NN 50000
#define EE 1600000
#define KHOPS 16
#define NBLK ((NN + 1023) / 1024)
#define PADCAP (EE + 4 * NN + 8)
#define HOPBLOCKS 740   // 148 SMs * 5 resident blocks -> single wave

// ---- device scratch (no allocations allowed) ----
__device__ int      g_deg[NN];
__device__ int      g_rowptr[NN + 1];
__device__ int      g_cursor[NN];
__device__ unsigned short g_col16[PADCAP];
__device__ float    g_dinv2[NN];    // (deg+1)^-1
__device__ float    g_rdinv[NN];    // (deg+1)^+1/2
__device__ float    g_dinv[NN];     // (deg+1)^-1/2
__device__ int      g_bsum[NBLK];
__device__ int      g_ctr[KHOPS + 1];
__device__ __half   g_x[KHOPS + 1][(NN + 1) * 128];  // y-states, fp16

__global__ void k_zero_deg() {
    int i = blockIdx.x * blockDim.x + threadIdx.x;
    if (i < NN) g_deg[i] = 0;
}

__global__ void k_degree(const int* __restrict__ dst) {
    int e = blockIdx.x * blockDim.x + threadIdx.x;
    if (e < EE) atomicAdd(&g_deg[dst[e]], 1);
}

// ---- scan phase 1 (+ fused dinv). Row length = deg+1 (self), padded to 4. ----
__global__ void k_scan1() {
    __shared__ int tmp[1024];
    int t = threadIdx.x;
    int i = blockIdx.x * 1024 + t;
    int dg = (i < NN) ? g_deg[i] : 0;
    if (i < NN) {
        float d = (float)(dg + 1);
        float r = rsqrtf(d);
        g_dinv[i]  = r;
        g_dinv2[i] = r * r;
        g_rdinv[i] = sqrtf(d);
    }
    int v = (i < NN) ? ((dg + 1 + 3) & ~3) : 0;
    tmp[t] = v;
    __syncthreads();
#pragma unroll
    for (int off = 1; off < 1024; off <<= 1) {
        int add = (t >= off) ? tmp[t - off] : 0;
        __syncthreads();
        tmp[t] += add;
        __syncthreads();
    }
    if (i < NN) g_rowptr[i] = tmp[t] - v;
    if (t == 1023) g_bsum[blockIdx.x] = tmp[t];
}

__global__ void k_scan2() {          // 64-thread parallel scan over NBLK block sums
    __shared__ int tmp[64];
    int t = threadIdx.x;
    int v = (t < NBLK) ? g_bsum[t] : 0;
    tmp[t] = v;
    __syncthreads();
#pragma unroll
    for (int off = 1; off < 64; off <<= 1) {
        int add = (t >= off) ? tmp[t - off] : 0;
        __syncthreads();
        tmp[t] += add;
        __syncthreads();
    }
    if (t < NBLK) g_bsum[t] = tmp[t] - v;
    if (t == 63) g_rowptr[NN] = tmp[t];
}

__global__ void k_scan3() {
    int i = blockIdx.x * 1024 + threadIdx.x;
    if (i < NN) {
        int r = g_rowptr[i] + g_bsum[blockIdx.x];
        g_rowptr[i] = r;
        g_cursor[i] = r;
    }
}

__global__ void k_fill(const int* __restrict__ src, const int* __restrict__ dst) {
    int e = blockIdx.x * blockDim.x + threadIdx.x;
    if (e < EE) {
        int d = dst[e];
        int p = atomicAdd(&g_cursor[d], 1);
        g_col16[p] = (unsigned short)src[e];
    }
}

// deterministic: warp-per-row SMEM rank sort; append self id; pad with 0xFFFF sentinel
__global__ void __launch_bounds__(256) k_sort() {
    __shared__ unsigned short buf[8][160];
    int warp = threadIdx.x >> 5, lane = threadIdx.x & 31;
    int r = blockIdx.x * 8 + warp;
    if (r >= NN) return;
    int beg  = g_rowptr[r];
    int deg  = g_deg[r];
    int plen = g_rowptr[r + 1] - beg;
    if (deg <= 160) {
        for (int i = lane; i < deg; i += 32) buf[warp][i] = g_col16[beg + i];
        __syncwarp();
        for (int i = lane; i < deg; i += 32) {
            int v = buf[warp][i];
            int rank = 0;
            for (int j = 0; j < deg; j++) {
                int u = buf[warp][j];
                rank += (u < v) || (u == v && j < i);
            }
            g_col16[beg + rank] = (unsigned short)v;
        }
    } else if (lane == 0) {          // practically unreachable fallback
        for (int i = beg + 1; i < beg + deg; i++) {
            unsigned short key = g_col16[i];
            int j = i - 1;
            while (j >= beg && g_col16[j] > key) { g_col16[j + 1] = g_col16[j]; j--; }
            g_col16[j + 1] = key;
        }
    }
    if (lane == 0) g_col16[beg + deg] = (unsigned short)r;       // self loop
    for (int i = deg + 1 + lane; i < plen; i += 32)
        g_col16[beg + i] = (unsigned short)0xFFFF;               // sentinel: no load
}

// y0 = dinv * x0 -> fp16; zero hop counters
__global__ void k_init(const float4* __restrict__ x0) {
    int i = blockIdx.x * blockDim.x + threadIdx.x;
    if (i < NN * 32) {
        int row = i >> 5;
        float d = g_dinv[row];
        float4 v = x0[i];
        uint2 u;
        __half2 lo = __floats2half2_rn(d * v.x, d * v.y);
        __half2 hi = __floats2half2_rn(d * v.z, d * v.w);
        u.x = *reinterpret_cast<unsigned*>(&lo);
        u.y = *reinterpret_cast<unsigned*>(&hi);
        ((uint2*)g_x[0])[i] = u;
    }
    if (i < KHOPS + 1) g_ctr[i] = 0;
}

__device__ __forceinline__ void acc2(float& ax, float& ay, float& az, float& aw, uint2 u) {
    __half2 h0 = *reinterpret_cast<__half2*>(&u.x);
    __half2 h1 = *reinterpret_cast<__half2*>(&u.y);
    float2 f0 = __half22float2(h0);
    float2 f1 = __half22float2(h1);
    ax += f0.x; ay += f0.y; az += f1.x; aw += f1.y;
}

__device__ __forceinline__ void acc8(float* a, uint4 u) {
    acc2(a[0], a[1], a[2], a[3], make_uint2(u.x, u.y));
    acc2(a[4], a[5], a[6], a[7], make_uint2(u.z, u.w));
}

// work-stealing hop (round-12 skeleton). Warp per node; lanes 0-15 EVEN slots,
// lanes 16-31 ODD slots; lane = one uint4 (16B) chunk of the 256B row -> LDG.128.
// Sentinel ids (>=NN) predicated off: padding generates zero traffic.
__global__ void __launch_bounds__(256, 5) k_hop(int k) {
    const __half* __restrict__ xin = g_x[k - 1];
    __half* __restrict__ xout = g_x[k];
    int lane = threadIdx.x & 31;
    int hi   = lane >> 4;        // even/odd slot class
    int c16  = lane & 15;        // 16-byte chunk of the row
    for (;;) {
        int base = 0;
        if (lane == 0) base = atomicAdd(&g_ctr[k], 2);
        base = __shfl_sync(0xffffffffu, base, 0);
        if (base >= NN) break;
        int nend = (base + 2 < NN) ? base + 2 : NN;
        for (int n = base; n < nend; n++) {
            float a[8];
#pragma unroll
            for (int q = 0; q < 8; q++) a[q] = 0.f;
            int j   = g_rowptr[n];
            int end = g_rowptr[n + 1];
            for (; j < end; j += 4) {            // 4 slots = 2 per half-warp / iter
                uint2 cc = *(const uint2*)(g_col16 + j);
                int cA = hi ? (int)(cc.x >> 16) : (int)(cc.x & 0xFFFF);
                int cB = hi ? (int)(cc.y >> 16) : (int)(cc.y & 0xFFFF);
                uint4 vA = make_uint4(0u, 0u, 0u, 0u);
                uint4 vB = make_uint4(0u, 0u, 0u, 0u);
                if (cA < NN) vA = ((const uint4*)(xin + (size_t)cA * 128))[c16];
                if (cB < NN) vB = ((const uint4*)(xin + (size_t)cB * 128))[c16];
                acc8(a, vA);
                acc8(a, vB);
            }
            // combine even/odd halves (fixed order -> deterministic)
#pragma unroll
            for (int q = 0; q < 8; q++)
                a[q] += __shfl_xor_sync(0xffffffffu, a[q], 16);
            if (hi == 0) {
                float s2 = g_dinv2[n];
                uint4 o;
                __half2 p0 = __floats2half2_rn(s2 * a[0], s2 * a[1]);
                __half2 p1 = __floats2half2_rn(s2 * a[2], s2 * a[3]);
                __half2 p2 = __floats2half2_rn(s2 * a[4], s2 * a[5]);
                __half2 p3 = __floats2half2_rn(s2 * a[6], s2 * a[7]);
                o.x = *reinterpret_cast<unsigned*>(&p0);
                o.y = *reinterpret_cast<unsigned*>(&p1);
                o.z = *reinterpret_cast<unsigned*>(&p2);
                o.w = *reinterpret_cast<unsigned*>(&p3);
                ((uint4*)(xout + (size_t)n * 128))[c16] = o;
            }
        }
    }
}

// Fused finalize + GEMM. h[m,:] = 0.05*x0 + (0.95/16)*rdinv*sum_k y_k, built in SMEM,
// then C[m,o] = sum_d h[m,d]*W[o,d] + bias[o]. 64-row tile.
__global__ void __launch_bounds__(256) k_gemm(const float4* __restrict__ x0,
                                              const float* __restrict__ Wt,
                                              const float* __restrict__ bias,
                                              float* __restrict__ out) {
    __shared__ float Hs[64][129];
    __shared__ float Ws[128][34];
    int tid = threadIdx.x;
    int row0 = blockIdx.x * 64;
    const float cf = 0.95f / 16.0f;

#pragma unroll
    for (int q = 0; q < 8; q++) {
        int p = tid + 256 * q;          // 0..2047
        int r = p >> 5, c4 = p & 31;
        int gr = row0 + r;
        float hx = 0.f, hy = 0.f, hz = 0.f, hw = 0.f;
        if (gr < NN) {
            float sx = 0.f, sy = 0.f, sz = 0.f, sw = 0.f;
#pragma unroll
            for (int k = 1; k <= KHOPS; k++) {
                uint2 u = ((const uint2*)(g_x[k] + (size_t)gr * 128))[c4];
                acc2(sx, sy, sz, sw, u);
            }
            float rd = g_rdinv[gr];
            float4 v = x0[gr * 32 + c4];
            hx = fmaf(cf * rd, sx, 0.05f * v.x);
            hy = fmaf(cf * rd, sy, 0.05f * v.y);
            hz = fmaf(cf * rd, sz, 0.05f * v.z);
            hw = fmaf(cf * rd, sw, 0.05f * v.w);
        }
        Hs[r][c4 * 4 + 0] = hx; Hs[r][c4 * 4 + 1] = hy;
        Hs[r][c4 * 4 + 2] = hz; Hs[r][c4 * 4 + 3] = hw;
    }

    int tx = tid & 15;    // out cols tx*8..+7
    int ty = tid >> 4;    // rows ty*4..+3
    float acc[4][8];
#pragma unroll
    for (int r = 0; r < 4; r++)
#pragma unroll
        for (int o = 0; o < 8; o++) acc[r][o] = 0.f;

    const float4* w4 = (const float4*)Wt;
    __syncthreads();
    for (int kc = 0; kc < 4; kc++) {
#pragma unroll
        for (int q = 0; q < 4; q++) {
            int idx = tid * 4 + q;       // 0..1023
            int o = idx >> 3, c4 = idx & 7;
            float4 v = w4[o * 32 + kc * 8 + c4];
            Ws[o][c4 * 4 + 0] = v.x; Ws[o][c4 * 4 + 1] = v.y;
            Ws[o][c4 * 4 + 2] = v.z; Ws[o][c4 * 4 + 3] = v.w;
        }
        __syncthreads();
#pragma unroll
        for (int kk = 0; kk < 32; kk++) {
            int kg = kc * 32 + kk;
            float hreg[4], wreg[8];
#pragma unroll
            for (int r = 0; r < 4; r++) hreg[r] = Hs[ty * 4 + r][kg];
#pragma unroll
            for (int o = 0; o < 8; o++) wreg[o] = Ws[tx * 8 + o][kk];
#pragma unroll
            for (int r = 0; r < 4; r++)
#pragma unroll
                for (int o = 0; o < 8; o++)
                    acc[r][o] = fmaf(hreg[r], wreg[o], acc[r][o]);
        }
        __syncthreads();
    }

    float b[8];
#pragma unroll
    for (int o = 0; o < 8; o++) b[o] = bias[tx * 8 + o];
    float4* out4 = (float4*)out;
#pragma unroll
    for (int r = 0; r < 4; r++) {
        int gr = row0 + ty * 4 + r;
        if (gr < NN) {
            float4 lo = make_float4(acc[r][0] + b[0], acc[r][1] + b[1],
                                    acc[r][2] + b[2], acc[r][3] + b[3]);
            float4 hi4 = make_float4(acc[r][4] + b[4], acc[r][5] + b[5],
                                     acc[r][6] + b[6], acc[r][7] + b[7]);
            out4[gr * 32 + tx * 2 + 0] = lo;
            out4[gr * 32 + tx * 2 + 1] = hi4;
        }
    }
}

extern "C" void kernel_launch(void* const* d_in, const int* in_sizes, int n_in,
                              void* d_out, int out_size) {
    const float* x0   = (const float*)d_in[0];
    const int*   ei   = (const int*)d_in[1];
    const float* Wt   = (const float*)d_in[2];
    const float* bias = (const float*)d_in[3];
    float*       out  = (float*)d_out;
    const int* src = ei;
    const int* dst = ei + EE;

    k_zero_deg<<<(NN + 255) / 256, 256>>>();
    k_degree<<<(EE + 255) / 256, 256>>>(dst);
    k_scan1<<<NBLK, 1024>>>();
    k_scan2<<<1, 64>>>();
    k_scan3<<<NBLK, 1024>>>();
    k_fill<<<(EE + 255) / 256, 256>>>(src, dst);
    k_sort<<<(NN + 7) / 8, 256>>>();
    k_init<<<(NN * 32 + 255) / 256, 256>>>((const float4*)x0);

    for (int k = 1; k <= KHOPS; k++)
        k_hop<<<HOPBLOCKS, 256>>>(k);

    k_gemm<<<(NN + 63) / 64, 256>>>((const float4*)x0, Wt, bias, out);
}

// round 15
// speedup vs baseline: 1.0457x; 1.0431x over previous
#include <cuda_runtime.h>
#include <cuda_fp16.h>

#define NN 50000
#define EE 1600000
#define KHOPS 16
#define NBLK ((NN + 1023) / 1024)
#define PADCAP (EE + 4 * NN + 8)
#define HOPBLOCKS 740   // 148 SMs * 5 resident blocks -> single wave

// ---- device scratch (no allocations allowed) ----
__device__ int      g_deg[NN];
__device__ int      g_rowptr[NN + 1];
__device__ int      g_cursor[NN];
__device__ unsigned short g_col16[PADCAP];
__device__ float    g_dinv2[NN];    // (deg+1)^-1
__device__ float    g_rdinv[NN];    // (deg+1)^+1/2
__device__ float    g_dinv[NN];     // (deg+1)^-1/2
__device__ int      g_bsum[NBLK];
__device__ int      g_ctr[KHOPS + 1];
__device__ __half   g_x[KHOPS + 1][(NN + 1) * 128];  // y-states, fp16; row NN = zeros

__global__ void k_zero_deg() {
    int i = blockIdx.x * blockDim.x + threadIdx.x;
    if (i < NN) g_deg[i] = 0;
}

__global__ void k_degree(const int* __restrict__ dst) {
    int e = blockIdx.x * blockDim.x + threadIdx.x;
    if (e < EE) atomicAdd(&g_deg[dst[e]], 1);
}

// ---- scan phase 1 (+ fused dinv). Row length = deg+1 (self), padded to 4. ----
__global__ void k_scan1() {
    __shared__ int tmp[1024];
    int t = threadIdx.x;
    int i = blockIdx.x * 1024 + t;
    int dg = (i < NN) ? g_deg[i] : 0;
    if (i < NN) {
        float d = (float)(dg + 1);
        float r = rsqrtf(d);
        g_dinv[i]  = r;
        g_dinv2[i] = r * r;
        g_rdinv[i] = sqrtf(d);
    }
    int v = (i < NN) ? ((dg + 1 + 3) & ~3) : 0;
    tmp[t] = v;
    __syncthreads();
#pragma unroll
    for (int off = 1; off < 1024; off <<= 1) {
        int add = (t >= off) ? tmp[t - off] : 0;
        __syncthreads();
        tmp[t] += add;
        __syncthreads();
    }
    if (i < NN) g_rowptr[i] = tmp[t] - v;
    if (t == 1023) g_bsum[blockIdx.x] = tmp[t];
}

__global__ void k_scan2() {          // 64-thread parallel scan over NBLK block sums
    __shared__ int tmp[64];
    int t = threadIdx.x;
    int v = (t < NBLK) ? g_bsum[t] : 0;
    tmp[t] = v;
    __syncthreads();
#pragma unroll
    for (int off = 1; off < 64; off <<= 1) {
        int add = (t >= off) ? tmp[t - off] : 0;
        __syncthreads();
        tmp[t] += add;
        __syncthreads();
    }
    if (t < NBLK) g_bsum[t] = tmp[t] - v;
    if (t == 63) g_rowptr[NN] = tmp[t];
}

__global__ void k_scan3() {
    int i = blockIdx.x * 1024 + threadIdx.x;
    if (i < NN) {
        int r = g_rowptr[i] + g_bsum[blockIdx.x];
        g_rowptr[i] = r;
        g_cursor[i] = r;
    }
}

__global__ void k_fill(const int* __restrict__ src, const int* __restrict__ dst) {
    int e = blockIdx.x * blockDim.x + threadIdx.x;
    if (e < EE) {
        int d = dst[e];
        int p = atomicAdd(&g_cursor[d], 1);
        g_col16[p] = (unsigned short)src[e];
    }
}

// deterministic: warp-per-row SMEM rank sort; append self id; pad with zero-row id NN
__global__ void __launch_bounds__(256) k_sort() {
    __shared__ unsigned short buf[8][160];
    int warp = threadIdx.x >> 5, lane = threadIdx.x & 31;
    int r = blockIdx.x * 8 + warp;
    if (r >= NN) return;
    int beg  = g_rowptr[r];
    int deg  = g_deg[r];
    int plen = g_rowptr[r + 1] - beg;
    if (deg <= 160) {
        for (int i = lane; i < deg; i += 32) buf[warp][i] = g_col16[beg + i];
        __syncwarp();
        for (int i = lane; i < deg; i += 32) {
            int v = buf[warp][i];
            int rank = 0;
            for (int j = 0; j < deg; j++) {
                int u = buf[warp][j];
                rank += (u < v) || (u == v && j < i);
            }
            g_col16[beg + rank] = (unsigned short)v;
        }
    } else if (lane == 0) {          // practically unreachable fallback
        for (int i = beg + 1; i < beg + deg; i++) {
            unsigned short key = g_col16[i];
            int j = i - 1;
            while (j >= beg && g_col16[j] > key) { g_col16[j + 1] = g_col16[j]; j--; }
            g_col16[j + 1] = key;
        }
    }
    if (lane == 0) g_col16[beg + deg] = (unsigned short)r;       // self loop
    for (int i = deg + 1 + lane; i < plen; i += 32)
        g_col16[beg + i] = (unsigned short)NN;                   // pad -> zero row
}

// y0 = dinv * x0 -> fp16; zero row NN of all buffers; zero hop counters
__global__ void k_init(const float4* __restrict__ x0) {
    int i = blockIdx.x * blockDim.x + threadIdx.x;
    if (i < NN * 32) {
        int row = i >> 5;
        float d = g_dinv[row];
        float4 v = x0[i];
        uint2 u;
        __half2 lo = __floats2half2_rn(d * v.x, d * v.y);
        __half2 hi = __floats2half2_rn(d * v.z, d * v.w);
        u.x = *reinterpret_cast<unsigned*>(&lo);
        u.y = *reinterpret_cast<unsigned*>(&hi);
        ((uint2*)g_x[0])[i] = u;
    }
    if (i < (KHOPS + 1) * 32)
        ((uint2*)g_x[i >> 5])[NN * 32 + (i & 31)] = make_uint2(0u, 0u);
    if (i < KHOPS + 1) g_ctr[i] = 0;
}

__device__ __forceinline__ void acc2(float& ax, float& ay, float& az, float& aw, uint2 u) {
    __half2 h0 = *reinterpret_cast<__half2*>(&u.x);
    __half2 h1 = *reinterpret_cast<__half2*>(&u.y);
    float2 f0 = __half22float2(h0);
    float2 f1 = __half22float2(h1);
    ax += f0.x; ay += f0.y; az += f1.x; aw += f1.y;
}

__device__ __forceinline__ void acc8(float* a, uint4 u) {
    acc2(a[0], a[1], a[2], a[3], make_uint2(u.x, u.y));
    acc2(a[4], a[5], a[6], a[7], make_uint2(u.z, u.w));
}

// work-stealing hop (round-12 skeleton, unconditional loads). Warp per node;
// lanes 0-15 EVEN list slots, lanes 16-31 ODD slots; lane = one uint4 (16B)
// chunk of the 256B row -> LDG.128. Padding ids point at the zero row.
__global__ void __launch_bounds__(256, 5) k_hop(int k) {
    const __half* __restrict__ xin = g_x[k - 1];
    __half* __restrict__ xout = g_x[k];
    int lane = threadIdx.x & 31;
    int hi   = lane >> 4;        // even/odd slot class
    int c16  = lane & 15;        // 16-byte chunk of the row
    for (;;) {
        int base = 0;
        if (lane == 0) base = atomicAdd(&g_ctr[k], 2);
        base = __shfl_sync(0xffffffffu, base, 0);
        if (base >= NN) break;
        int nend = (base + 2 < NN) ? base + 2 : NN;
        for (int n = base; n < nend; n++) {
            float a[8];
#pragma unroll
            for (int q = 0; q < 8; q++) a[q] = 0.f;
            int j   = g_rowptr[n];
            int end = g_rowptr[n + 1];
            for (; j < end; j += 4) {            // 4 slots = 2 per half-warp / iter
                uint2 cc = *(const uint2*)(g_col16 + j);
                int cA = hi ? (int)(cc.x >> 16) : (int)(cc.x & 0xFFFF);
                int cB = hi ? (int)(cc.y >> 16) : (int)(cc.y & 0xFFFF);
                uint4 vA = ((const uint4*)(xin + (size_t)cA * 128))[c16];
                uint4 vB = ((const uint4*)(xin + (size_t)cB * 128))[c16];
                acc8(a, vA);
                acc8(a, vB);
            }
            // combine even/odd halves (fixed order -> deterministic)
#pragma unroll
            for (int q = 0; q < 8; q++)
                a[q] += __shfl_xor_sync(0xffffffffu, a[q], 16);
            if (hi == 0) {
                float s2 = g_dinv2[n];
                uint4 o;
                __half2 p0 = __floats2half2_rn(s2 * a[0], s2 * a[1]);
                __half2 p1 = __floats2half2_rn(s2 * a[2], s2 * a[3]);
                __half2 p2 = __floats2half2_rn(s2 * a[4], s2 * a[5]);
                __half2 p3 = __floats2half2_rn(s2 * a[6], s2 * a[7]);
                o.x = *reinterpret_cast<unsigned*>(&p0);
                o.y = *reinterpret_cast<unsigned*>(&p1);
                o.z = *reinterpret_cast<unsigned*>(&p2);
                o.w = *reinterpret_cast<unsigned*>(&p3);
                ((uint4*)(xout + (size_t)n * 128))[c16] = o;
            }
        }
    }
}

// Fused finalize + GEMM. h[m,:] = 0.05*x0 + (0.95/16)*rdinv*sum_k y_k, built in SMEM,
// then C[m,o] = sum_d h[m,d]*W[o,d] + bias[o]. 64-row tile.
__global__ void __launch_bounds__(256) k_gemm(const float4* __restrict__ x0,
                                              const float* __restrict__ Wt,
                                              const float* __restrict__ bias,
                                              float* __restrict__ out) {
    __shared__ float Hs[64][129];
    __shared__ float Ws[128][34];
    int tid = threadIdx.x;
    int row0 = blockIdx.x * 64;
    const float cf = 0.95f / 16.0f;

#pragma unroll
    for (int q = 0; q < 8; q++) {
        int p = tid + 256 * q;          // 0..2047
        int r = p >> 5, c4 = p & 31;
        int gr = row0 + r;
        float hx = 0.f, hy = 0.f, hz = 0.f, hw = 0.f;
        if (gr < NN) {
            float sx = 0.f, sy = 0.f, sz = 0.f, sw = 0.f;
#pragma unroll
            for (int k = 1; k <= KHOPS; k++) {
                uint2 u = ((const uint2*)(g_x[k] + (size_t)gr * 128))[c4];
                acc2(sx, sy, sz, sw, u);
            }
            float rd = g_rdinv[gr];
            float4 v = x0[gr * 32 + c4];
            hx = fmaf(cf * rd, sx, 0.05f * v.x);
            hy = fmaf(cf * rd, sy, 0.05f * v.y);
            hz = fmaf(cf * rd, sz, 0.05f * v.z);
            hw = fmaf(cf * rd, sw, 0.05f * v.w);
        }
        Hs[r][c4 * 4 + 0] = hx; Hs[r][c4 * 4 + 1] = hy;
        Hs[r][c4 * 4 + 2] = hz; Hs[r][c4 * 4 + 3] = hw;
    }

    int tx = tid & 15;    // out cols tx*8..+7
    int ty = tid >> 4;    // rows ty*4..+3
    float acc[4][8];
#pragma unroll
    for (int r = 0; r < 4; r++)
#pragma unroll
        for (int o = 0; o < 8; o++) acc[r][o] = 0.f;

    const float4* w4 = (const float4*)Wt;
    __syncthreads();
    for (int kc = 0; kc < 4; kc++) {
#pragma unroll
        for (int q = 0; q < 4; q++) {
            int idx = tid * 4 + q;       // 0..1023
            int o = idx >> 3, c4 = idx & 7;
            float4 v = w4[o * 32 + kc * 8 + c4];
            Ws[o][c4 * 4 + 0] = v.x; Ws[o][c4 * 4 + 1] = v.y;
            Ws[o][c4 * 4 + 2] = v.z; Ws[o][c4 * 4 + 3] = v.w;
        }
        __syncthreads();
#pragma unroll
        for (int kk = 0; kk < 32; kk++) {
            int kg = kc * 32 + kk;
            float hreg[4], wreg[8];
#pragma unroll
            for (int r = 0; r < 4; r++) hreg[r] = Hs[ty * 4 + r][kg];
#pragma unroll
            for (int o = 0; o < 8; o++) wreg[o] = Ws[tx * 8 + o][kk];
#pragma unroll
            for (int r = 0; r < 4; r++)
#pragma unroll
                for (int o = 0; o < 8; o++)
                    acc[r][o] = fmaf(hreg[r], wreg[o], acc[r][o]);
        }
        __syncthreads();
    }

    float b[8];
#pragma unroll
    for (int o = 0; o < 8; o++) b[o] = bias[tx * 8 + o];
    float4* out4 = (float4*)out;
#pragma unroll
    for (int r = 0; r < 4; r++) {
        int gr = row0 + ty * 4 + r;
        if (gr < NN) {
            float4 lo = make_float4(acc[r][0] + b[0], acc[r][1] + b[1],
                                    acc[r][2] + b[2], acc[r][3] + b[3]);
            float4 hi4 = make_float4(acc[r][4] + b[4], acc[r][5] + b[5],
                                     acc[r][6] + b[6], acc[r][7] + b[7]);
            out4[gr * 32 + tx * 2 + 0] = lo;
            out4[gr * 32 + tx * 2 + 1] = hi4;
        }
    }
}

extern "C" void kernel_launch(void* const* d_in, const int* in_sizes, int n_in,
                              void* d_out, int out_size) {
    const float* x0   = (const float*)d_in[0];
    const int*   ei   = (const int*)d_in[1];
    const float* Wt   = (const float*)d_in[2];
    const float* bias = (const float*)d_in[3];
    float*       out  = (float*)d_out;
    const int* src = ei;
    const int* dst = ei + EE;

    k_zero_deg<<<(NN + 255) / 256, 256>>>();
    k_degree<<<(EE + 255) / 256, 256>>>(dst);
    k_scan1<<<NBLK, 1024>>>();
    k_scan2<<<1, 64>>>();
    k_scan3<<<NBLK, 1024>>>();
    k_fill<<<(EE + 255) / 256, 256>>>(src, dst);
    k_sort<<<(NN + 7) / 8, 256>>>();
    k_init<<<(NN * 32 + 255) / 256, 256>>>((const float4*)x0);

    for (int k = 1; k <= KHOPS; k++)
        k_hop<<<HOPBLOCKS, 256>>>(k);

    k_gemm<<<(NN + 63) / 64, 256>>>((const float4*)x0, Wt, bias, out);
}